// round 9
// baseline (speedup 1.0000x reference)
#include <cuda_runtime.h>
#include <math.h>
#include <stdint.h>

#define T_SEQ 2048
#define B_SZ  2
#define C_DIM 1024
#define H_NUM 16
#define D_HEAD 64
#define M_ROWS (T_SEQ * B_SZ)   // 4096

__device__ float g_q[(size_t)B_SZ * H_NUM * T_SEQ * D_HEAD];
__device__ float g_k[(size_t)B_SZ * H_NUM * T_SEQ * D_HEAD];
__device__ float g_v[(size_t)B_SZ * H_NUM * T_SEQ * D_HEAD];
__device__ float g_xc[(size_t)M_ROWS * C_DIM];        // x, tf32-rounded, permuted cols
__device__ float g_wc[4][(size_t)C_DIM * C_DIM];      // Wq,Wk,Wv,Wo rounded+permuted
__device__ float g_ctxp[(size_t)M_ROWS * C_DIM];      // ctx, rounded+permuted

__device__ __forceinline__ float cvt_tf32(float x) {
    uint32_t r;
    asm("cvt.rna.tf32.f32 %0, %1;" : "=r"(r) : "f"(x));
    return __uint_as_float(r);
}

// Fast exp on the FFMA pipe. |rel err| ~2e-6.
__device__ __forceinline__ float fast_exp(float x) {
    x = fmaxf(x, -80.f);
    float y = x * 1.44269504f;
    float t = y + 12582912.f;
    int   n = __float_as_int(t) - 0x4B400000;
    float f = y - (t - 12582912.f);
    float p = 0.00133335581f;
    p = fmaf(p, f, 0.00961812911f);
    p = fmaf(p, f, 0.0555041087f);
    p = fmaf(p, f, 0.240226507f);
    p = fmaf(p, f, 0.69314718056f);
    p = fmaf(p, f, 1.0f);
    return p * __int_as_float((n + 127) << 23);
}

__device__ __forceinline__ void mma_tf32(float c[4], const uint32_t a[4],
                                         uint32_t b0, uint32_t b1) {
    asm volatile(
        "mma.sync.aligned.m16n8k8.row.col.f32.tf32.tf32.f32 "
        "{%0,%1,%2,%3}, {%4,%5,%6,%7}, {%8,%9}, {%0,%1,%2,%3};"
        : "+f"(c[0]), "+f"(c[1]), "+f"(c[2]), "+f"(c[3])
        : "r"(a[0]), "r"(a[1]), "r"(a[2]), "r"(a[3]), "r"(b0), "r"(b1));
}

#define CP16(dst_u32, src_ptr) \
    asm volatile("cp.async.cg.shared.global [%0], [%1], 16;" \
                 :: "r"(dst_u32), "l"(src_ptr))
#define CP_COMMIT() asm volatile("cp.async.commit_group;" ::: "memory")
#define CP_WAIT1()  asm volatile("cp.async.wait_group 1;" ::: "memory")

// ---------------------------------------------------------------------------
// Pre-convert: round to tf32 and permute columns within groups of 8:
//   pos(k) = (k & ~7) | ((k & 3) << 1) | ((k >> 2) & 1)
// so fragment pairs (k, k+4) become adjacent -> LDS.64 in the GEMMs.
// ---------------------------------------------------------------------------
#define X_F4 (M_ROWS * C_DIM / 4)   // 1048576
#define W_F4 (C_DIM * C_DIM / 4)    // 262144

__global__ __launch_bounds__(256) void preconvert_kernel(
    const float* __restrict__ x,  const float* __restrict__ Wq,
    const float* __restrict__ Wk, const float* __restrict__ Wv,
    const float* __restrict__ Wo)
{
    int g = blockIdx.x * 256 + threadIdx.x;
    const float* src;
    float* dst;
    int off;
    if (g < X_F4) {
        src = x; dst = g_xc; off = g;
    } else {
        int r = g - X_F4;
        int t = r / W_F4;
        off = r - t * W_F4;
        src = (t == 0) ? Wq : (t == 1) ? Wk : (t == 2) ? Wv : Wo;
        dst = g_wc[t];
    }
    float4 v = ((const float4*)src)[off];
    int fi   = off * 4;
    int col4 = fi & (C_DIM - 1);
    int rowb = fi - col4;
    int pb   = (col4 & ~7) + ((col4 >> 2) & 1);
    dst[rowb + pb    ] = cvt_tf32(v.x);
    dst[rowb + pb + 2] = cvt_tf32(v.y);
    dst[rowb + pb + 4] = cvt_tf32(v.z);
    dst[rowb + pb + 6] = cvt_tf32(v.w);
}

// ---------------------------------------------------------------------------
// TF32 NT GEMM v7: CTA 64x128, BK=32, 256 threads = 8 warps (2x4),
// warp tile 32x32 (2 m x 4 n frags) -> 1.0 LDS.64 per mma.
// 3-stage cp.async pipeline (prefetch distance 2, wait_group 1).
// SPAD=40 -> conflict-free LDS.64 on pre-permuted data, no cvt in loop.
// smem: 3 * (64+128)*40*4 = 92160 B -> 2 CTAs/SM (16 warps).
// ---------------------------------------------------------------------------
#define BM 64
#define BN 128
#define BK 32
#define SPAD 40
#define A_F (BM * SPAD)                 // 2560 floats
#define B_F (BN * SPAD)                 // 5120 floats
#define STAGE_F (A_F + B_F)             // 7680 floats
#define NSTAGE 3
#define GEMM_SMEM (NSTAGE * STAGE_F * 4)  // 92160 bytes

__device__ __forceinline__ void issue_stage(uint32_t s_a, uint32_t s_b,
                                            const float* __restrict__ A,
                                            const float* __restrict__ W,
                                            int bm, int bn, int k0, int tid) {
    const int row0 = tid >> 3;           // 0..31
    const int c4   = (tid & 7) * 4;      // 0..28
    #pragma unroll
    for (int i = 0; i < 2; i++) {
        int r = row0 + i * 32;
        uint32_t d = s_a + (uint32_t)((r * SPAD + c4) * 4);
        CP16(d, A + (size_t)(bm + r) * C_DIM + k0 + c4);
    }
    #pragma unroll
    for (int i = 0; i < 4; i++) {
        int r = row0 + i * 32;
        uint32_t d = s_b + (uint32_t)((r * SPAD + c4) * 4);
        CP16(d, W + (size_t)(bn + r) * C_DIM + k0 + c4);
    }
}

__device__ __forceinline__ void tile_mma4(const float* __restrict__ As,
                                          const float* __restrict__ Bs,
                                          float c[2][4][4],
                                          int wm, int wn, int gid, int tig) {
    #pragma unroll
    for (int kk = 0; kk < 4; kk++) {
        const int k2 = kk * 8 + tig * 2;   // permuted col of (k, k+4) pair
        uint32_t a[2][4];
        #pragma unroll
        for (int mt = 0; mt < 2; mt++) {
            int r = wm * 32 + mt * 16 + gid;
            float2 f0 = *(const float2*)&As[(size_t)r * SPAD + k2];        // (a0,a2)
            float2 f1 = *(const float2*)&As[(size_t)(r + 8) * SPAD + k2];  // (a1,a3)
            a[mt][0] = __float_as_uint(f0.x);
            a[mt][1] = __float_as_uint(f1.x);
            a[mt][2] = __float_as_uint(f0.y);
            a[mt][3] = __float_as_uint(f1.y);
        }
        #pragma unroll
        for (int nt = 0; nt < 4; nt++) {
            int cn = wn * 32 + nt * 8 + gid;
            float2 fb = *(const float2*)&Bs[(size_t)cn * SPAD + k2];       // (b0,b1)
            #pragma unroll
            for (int mt = 0; mt < 2; mt++)
                mma_tf32(c[mt][nt], a[mt],
                         __float_as_uint(fb.x), __float_as_uint(fb.y));
        }
    }
}

__device__ __forceinline__ void gemm_mainloop(const float* __restrict__ A,
                                              const float* __restrict__ W,
                                              float c[2][4][4],
                                              int bm, int bn, int tid) {
    extern __shared__ float dyn[];
    uint32_t sbase;
    asm("{ .reg .u64 t; cvta.to.shared.u64 t, %1; cvt.u32.u64 %0, t; }"
        : "=r"(sbase) : "l"(dyn));

    const int lane = tid & 31, wid = tid >> 5;
    const int gid = lane >> 2, tig = lane & 3;
    const int wm = wid >> 2, wn = wid & 3;

    const int NIT = C_DIM / BK;   // 32

    // prologue: stages 0,1 into slots 0,1
    #pragma unroll
    for (int s = 0; s < 2; s++) {
        uint32_t s_a = sbase + (uint32_t)(s * STAGE_F * 4);
        uint32_t s_b = s_a + (uint32_t)(A_F * 4);
        issue_stage(s_a, s_b, A, W, bm, bn, s * BK, tid);
        CP_COMMIT();
    }

    int slot = 0;          // slot of stage i
    int nslot = 2;         // slot for stage i+2
    for (int i = 0; i < NIT; i++) {
        CP_WAIT1();
        __syncthreads();

        int nxt = i + 2;
        if (nxt < NIT) {
            uint32_t s_a = sbase + (uint32_t)(nslot * STAGE_F * 4);
            uint32_t s_b = s_a + (uint32_t)(A_F * 4);
            issue_stage(s_a, s_b, A, W, bm, bn, nxt * BK, tid);
        }
        CP_COMMIT();

        const float* As = dyn + (size_t)slot * STAGE_F;
        const float* Bs = As + A_F;
        tile_mma4(As, Bs, c, wm, wn, gid, tig);

        slot  = (slot == 2) ? 0 : slot + 1;
        nslot = (nslot == 2) ? 0 : nslot + 1;
    }
}

// QKV fused: blockIdx.z selects weight + destination (remapped to B,H,T,D)
__global__ __launch_bounds__(256, 2) void gemm_qkv_kernel()
{
    const float* W = g_wc[blockIdx.z];
    float* dst     = (blockIdx.z == 0) ? g_q : (blockIdx.z == 1) ? g_k : g_v;

    const int tid = threadIdx.x;
    const int lane = tid & 31, wid = tid >> 5;
    const int gid = lane >> 2, tig = lane & 3;
    const int wm = wid >> 2, wn = wid & 3;
    const int bm = blockIdx.y * BM, bn = blockIdx.x * BN;

    float c[2][4][4];
    #pragma unroll
    for (int mt = 0; mt < 2; mt++)
        #pragma unroll
        for (int nt = 0; nt < 4; nt++)
            #pragma unroll
            for (int i = 0; i < 4; i++) c[mt][nt][i] = 0.f;

    gemm_mainloop(g_xc, W, c, bm, bn, tid);

    #pragma unroll
    for (int mt = 0; mt < 2; mt++)
        #pragma unroll
        for (int nt = 0; nt < 4; nt++) {
            int row0 = bm + wm * 32 + mt * 16 + gid;
            int n    = bn + wn * 32 + nt * 8 + tig * 2;
            int hh = n >> 6, d = n & 63;
            #pragma unroll
            for (int i = 0; i < 2; i++) {
                int m = row0 + i * 8;
                int t = m >> 1, bb = m & 1;
                *(float2*)&dst[(((size_t)bb * H_NUM + hh) * T_SEQ + t) * D_HEAD + d] =
                    make_float2(c[mt][nt][i * 2], c[mt][nt][i * 2 + 1]);
            }
        }
}

__global__ __launch_bounds__(256, 2) void gemm_out_kernel(float* __restrict__ out)
{
    const int tid = threadIdx.x;
    const int lane = tid & 31, wid = tid >> 5;
    const int gid = lane >> 2, tig = lane & 3;
    const int wm = wid >> 2, wn = wid & 3;
    const int bm = blockIdx.y * BM, bn = blockIdx.x * BN;

    float c[2][4][4];
    #pragma unroll
    for (int mt = 0; mt < 2; mt++)
        #pragma unroll
        for (int nt = 0; nt < 4; nt++)
            #pragma unroll
            for (int i = 0; i < 4; i++) c[mt][nt][i] = 0.f;

    gemm_mainloop(g_ctxp, g_wc[3], c, bm, bn, tid);

    #pragma unroll
    for (int mt = 0; mt < 2; mt++)
        #pragma unroll
        for (int nt = 0; nt < 4; nt++) {
            int row0 = bm + wm * 32 + mt * 16 + gid;
            int col0 = bn + wn * 32 + nt * 8 + tig * 2;
            *(float2*)(out + (size_t)row0 * C_DIM + col0) =
                make_float2(c[mt][nt][0], c[mt][nt][1]);
            *(float2*)(out + (size_t)(row0 + 8) * C_DIM + col0) =
                make_float2(c[mt][nt][2], c[mt][nt][3]);
        }
}

// ---------------------------------------------------------------------------
// Tensor-core causal flash attention (unchanged from round 8). Epilogue
// writes ctx tf32-rounded + column-permuted so the out-proj GEMM is cvt-free.
// 128 threads = 4 warps, Q-tile 64, K/V tiles 64x64, K column-pair permute.
// ---------------------------------------------------------------------------
__global__ __launch_bounds__(128) void attn_tc_kernel()
{
    const int qb = (gridDim.x - 1) - blockIdx.x;
    const int h  = blockIdx.y;
    const int b  = blockIdx.z;
    const size_t base = (((size_t)b * H_NUM + h) * T_SEQ) * D_HEAD;
    const float* Qp = g_q + base;
    const float* Kp = g_k + base;
    const float* Vp = g_v + base;

    const int tid  = threadIdx.x;
    const int lane = tid & 31;
    const int wid  = tid >> 5;
    const int gid  = lane >> 2;
    const int tig  = lane & 3;

    __shared__ float Ks[64][72];  // permuted columns
    __shared__ float Vs[64][72];

    const int t0 = qb * 64 + wid * 16 + gid;
    const int t1 = t0 + 8;

    uint32_t qa[8][4];
    #pragma unroll
    for (int kk = 0; kk < 8; kk++) {
        qa[kk][0] = __float_as_uint(cvt_tf32(Qp[(size_t)t0 * 64 + kk * 8 + tig] * 0.125f));
        qa[kk][1] = __float_as_uint(cvt_tf32(Qp[(size_t)t1 * 64 + kk * 8 + tig] * 0.125f));
        qa[kk][2] = __float_as_uint(cvt_tf32(Qp[(size_t)t0 * 64 + kk * 8 + tig + 4] * 0.125f));
        qa[kk][3] = __float_as_uint(cvt_tf32(Qp[(size_t)t1 * 64 + kk * 8 + tig + 4] * 0.125f));
    }

    float m0 = -1e30f, m1 = -1e30f, l0 = 0.f, l1 = 0.f;
    float o[8][4];
    #pragma unroll
    for (int nt = 0; nt < 8; nt++)
        #pragma unroll
        for (int i = 0; i < 4; i++) o[nt][i] = 0.f;

    const int nkb = qb + 1;
    for (int kb = 0; kb < nkb; kb++) {
        #pragma unroll
        for (int it = 0; it < 8; it++) {
            int idx = tid + it * 128;
            int r = idx >> 4;
            int c = (idx & 15) * 4;
            float4 kv = *(const float4*)(Kp + (size_t)(kb * 64 + r) * 64 + c);
            int pb = ((c >> 3) << 3) + ((c >> 2) & 1);
            Ks[r][pb    ] = cvt_tf32(kv.x);
            Ks[r][pb + 2] = cvt_tf32(kv.y);
            Ks[r][pb + 4] = cvt_tf32(kv.z);
            Ks[r][pb + 6] = cvt_tf32(kv.w);
            float4 vv = *(const float4*)(Vp + (size_t)(kb * 64 + r) * 64 + c);
            *(float4*)&Vs[r][c] = make_float4(cvt_tf32(vv.x), cvt_tf32(vv.y),
                                              cvt_tf32(vv.z), cvt_tf32(vv.w));
        }
        __syncthreads();

        float s[8][4];
        #pragma unroll
        for (int nt = 0; nt < 8; nt++)
            #pragma unroll
            for (int i = 0; i < 4; i++) s[nt][i] = 0.f;

        #pragma unroll
        for (int kk = 0; kk < 8; kk++) {
            #pragma unroll
            for (int nt = 0; nt < 8; nt++) {
                float2 kbf = *(const float2*)&Ks[nt * 8 + gid][kk * 8 + tig * 2];
                mma_tf32(s[nt], qa[kk], __float_as_uint(kbf.x), __float_as_uint(kbf.y));
            }
        }

        if (kb == qb) {
            #pragma unroll
            for (int nt = 0; nt < 8; nt++) {
                int cg = kb * 64 + nt * 8 + tig * 2;
                if (cg     > t0) s[nt][0] = -1e30f;
                if (cg + 1 > t0) s[nt][1] = -1e30f;
                if (cg     > t1) s[nt][2] = -1e30f;
                if (cg + 1 > t1) s[nt][3] = -1e30f;
            }
        }

        float mb0 = m0, mb1 = m1;
        #pragma unroll
        for (int nt = 0; nt < 8; nt++) {
            mb0 = fmaxf(mb0, fmaxf(s[nt][0], s[nt][1]));
            mb1 = fmaxf(mb1, fmaxf(s[nt][2], s[nt][3]));
        }
        mb0 = fmaxf(mb0, __shfl_xor_sync(0xffffffffu, mb0, 1));
        mb0 = fmaxf(mb0, __shfl_xor_sync(0xffffffffu, mb0, 2));
        mb1 = fmaxf(mb1, __shfl_xor_sync(0xffffffffu, mb1, 1));
        mb1 = fmaxf(mb1, __shfl_xor_sync(0xffffffffu, mb1, 2));

        float corr0 = fast_exp(m0 - mb0);
        float corr1 = fast_exp(m1 - mb1);
        m0 = mb0; m1 = mb1;
        l0 *= corr0; l1 *= corr1;
        #pragma unroll
        for (int nt = 0; nt < 8; nt++) {
            o[nt][0] *= corr0; o[nt][1] *= corr0;
            o[nt][2] *= corr1; o[nt][3] *= corr1;
        }

        #pragma unroll
        for (int nt = 0; nt < 8; nt++) {
            s[nt][0] = fast_exp(s[nt][0] - m0);
            s[nt][1] = fast_exp(s[nt][1] - m0);
            s[nt][2] = fast_exp(s[nt][2] - m1);
            s[nt][3] = fast_exp(s[nt][3] - m1);
            l0 += s[nt][0] + s[nt][1];
            l1 += s[nt][2] + s[nt][3];
        }

        #pragma unroll
        for (int kk = 0; kk < 8; kk++) {
            int src  = (lane & ~3) | (tig >> 1);
            int src2 = src + 2;
            float v00 = __shfl_sync(0xffffffffu, s[kk][0], src);
            float v01 = __shfl_sync(0xffffffffu, s[kk][1], src);
            float v10 = __shfl_sync(0xffffffffu, s[kk][2], src);
            float v11 = __shfl_sync(0xffffffffu, s[kk][3], src);
            float w00 = __shfl_sync(0xffffffffu, s[kk][0], src2);
            float w01 = __shfl_sync(0xffffffffu, s[kk][1], src2);
            float w10 = __shfl_sync(0xffffffffu, s[kk][2], src2);
            float w11 = __shfl_sync(0xffffffffu, s[kk][3], src2);
            bool odd = (tig & 1);
            uint32_t pa[4];
            pa[0] = __float_as_uint(cvt_tf32(odd ? v01 : v00));
            pa[1] = __float_as_uint(cvt_tf32(odd ? v11 : v10));
            pa[2] = __float_as_uint(cvt_tf32(odd ? w01 : w00));
            pa[3] = __float_as_uint(cvt_tf32(odd ? w11 : w10));
            #pragma unroll
            for (int nt = 0; nt < 8; nt++) {
                uint32_t b0 = __float_as_uint(Vs[kk * 8 + tig    ][nt * 8 + gid]);
                uint32_t b1 = __float_as_uint(Vs[kk * 8 + tig + 4][nt * 8 + gid]);
                mma_tf32(o[nt], pa, b0, b1);
            }
        }
        __syncthreads();
    }

    l0 += __shfl_xor_sync(0xffffffffu, l0, 1);
    l0 += __shfl_xor_sync(0xffffffffu, l0, 2);
    l1 += __shfl_xor_sync(0xffffffffu, l1, 1);
    l1 += __shfl_xor_sync(0xffffffffu, l1, 2);
    float inv0 = 1.f / l0;
    float inv1 = 1.f / l1;

    // write ctx rounded + column-permuted (within groups of 8)
    const int k0 = tig * 2;
    const int p0 = ((k0 & 3) << 1) | ((k0 >> 2) & 1);
    const int p1 = (((k0 + 1) & 3) << 1) | (((k0 + 1) >> 2) & 1);
    #pragma unroll
    for (int nt = 0; nt < 8; nt++) {
        int cb = h * 64 + nt * 8;
        size_t r0 = ((size_t)t0 * B_SZ + b) * C_DIM + cb;
        size_t r1 = ((size_t)t1 * B_SZ + b) * C_DIM + cb;
        g_ctxp[r0 + p0] = cvt_tf32(o[nt][0] * inv0);
        g_ctxp[r0 + p1] = cvt_tf32(o[nt][1] * inv0);
        g_ctxp[r1 + p0] = cvt_tf32(o[nt][2] * inv1);
        g_ctxp[r1 + p1] = cvt_tf32(o[nt][3] * inv1);
    }
}

// ---------------------------------------------------------------------------
extern "C" void kernel_launch(void* const* d_in, const int* in_sizes, int n_in,
                              void* d_out, int out_size)
{
    const float* x  = (const float*)d_in[0];
    const float* Wq = (const float*)d_in[1];
    const float* Wk = (const float*)d_in[2];
    const float* Wv = (const float*)d_in[3];
    const float* Wo = (const float*)d_in[4];
    float* out = (float*)d_out;

    cudaFuncSetAttribute(gemm_qkv_kernel,
                         cudaFuncAttributeMaxDynamicSharedMemorySize, GEMM_SMEM);
    cudaFuncSetAttribute(gemm_out_kernel,
                         cudaFuncAttributeMaxDynamicSharedMemorySize, GEMM_SMEM);

    int nconv = (X_F4 + 4 * W_F4) / 256;     // 8192 blocks
    preconvert_kernel<<<nconv, 256>>>(x, Wq, Wk, Wv, Wo);

    dim3 gq(C_DIM / BN, M_ROWS / BM, 3);     // (8, 64, 3)
    gemm_qkv_kernel<<<gq, 256, GEMM_SMEM>>>();

    dim3 ga(T_SEQ / 64, H_NUM, B_SZ);        // (32, 16, 2)
    attn_tc_kernel<<<ga, 128>>>();

    dim3 go(C_DIM / BN, M_ROWS / BM);        // (8, 64)
    gemm_out_kernel<<<go, 256, GEMM_SMEM>>>(out);
}

// round 11
// speedup vs baseline: 1.1489x; 1.1489x over previous
#include <cuda_runtime.h>
#include <math.h>
#include <stdint.h>

#define T_SEQ 2048
#define B_SZ  2
#define C_DIM 1024
#define H_NUM 16
#define D_HEAD 64
#define M_ROWS (T_SEQ * B_SZ)   // 4096

// Q: pre-scaled (x0.125), tf32-rounded, column-permuted (groups of 8)
// K: tf32-rounded, column-permuted
// V: tf32-rounded, natural layout
__device__ float g_q[(size_t)B_SZ * H_NUM * T_SEQ * D_HEAD];
__device__ float g_k[(size_t)B_SZ * H_NUM * T_SEQ * D_HEAD];
__device__ float g_v[(size_t)B_SZ * H_NUM * T_SEQ * D_HEAD];
__device__ float g_xc[(size_t)M_ROWS * C_DIM];        // x, tf32-rounded, permuted cols
__device__ float g_wc[4][(size_t)C_DIM * C_DIM];      // Wq,Wk,Wv,Wo rounded+permuted
__device__ float g_ctxp[(size_t)M_ROWS * C_DIM];      // ctx, rounded+permuted

__device__ __forceinline__ float cvt_tf32(float x) {
    uint32_t r;
    asm("cvt.rna.tf32.f32 %0, %1;" : "=r"(r) : "f"(x));
    return __uint_as_float(r);
}

// Fast exp on the FFMA pipe. |rel err| ~2e-6.
__device__ __forceinline__ float fast_exp(float x) {
    x = fmaxf(x, -80.f);
    float y = x * 1.44269504f;
    float t = y + 12582912.f;
    int   n = __float_as_int(t) - 0x4B400000;
    float f = y - (t - 12582912.f);
    float p = 0.00133335581f;
    p = fmaf(p, f, 0.00961812911f);
    p = fmaf(p, f, 0.0555041087f);
    p = fmaf(p, f, 0.240226507f);
    p = fmaf(p, f, 0.69314718056f);
    p = fmaf(p, f, 1.0f);
    return p * __int_as_float((n + 127) << 23);
}

__device__ __forceinline__ void mma_tf32(float c[4], const uint32_t a[4],
                                         uint32_t b0, uint32_t b1) {
    asm volatile(
        "mma.sync.aligned.m16n8k8.row.col.f32.tf32.tf32.f32 "
        "{%0,%1,%2,%3}, {%4,%5,%6,%7}, {%8,%9}, {%0,%1,%2,%3};"
        : "+f"(c[0]), "+f"(c[1]), "+f"(c[2]), "+f"(c[3])
        : "r"(a[0]), "r"(a[1]), "r"(a[2]), "r"(a[3]), "r"(b0), "r"(b1));
}

#define CP16(dst_u32, src_ptr) \
    asm volatile("cp.async.cg.shared.global [%0], [%1], 16;" \
                 :: "r"(dst_u32), "l"(src_ptr))
#define CP_COMMIT() asm volatile("cp.async.commit_group;" ::: "memory")
#define CP_WAIT0()  asm volatile("cp.async.wait_group 0;" ::: "memory")
#define CP_WAIT1()  asm volatile("cp.async.wait_group 1;" ::: "memory")

// ---------------------------------------------------------------------------
// Pre-convert: round to tf32 and permute columns within groups of 8:
//   pos(k) = (k & ~7) | ((k & 3) << 1) | ((k >> 2) & 1)
// ---------------------------------------------------------------------------
#define X_F4 (M_ROWS * C_DIM / 4)   // 1048576
#define W_F4 (C_DIM * C_DIM / 4)    // 262144

__global__ __launch_bounds__(256) void preconvert_kernel(
    const float* __restrict__ x,  const float* __restrict__ Wq,
    const float* __restrict__ Wk, const float* __restrict__ Wv,
    const float* __restrict__ Wo)
{
    int g = blockIdx.x * 256 + threadIdx.x;
    const float* src;
    float* dst;
    int off;
    if (g < X_F4) {
        src = x; dst = g_xc; off = g;
    } else {
        int r = g - X_F4;
        int t = r / W_F4;
        off = r - t * W_F4;
        src = (t == 0) ? Wq : (t == 1) ? Wk : (t == 2) ? Wv : Wo;
        dst = g_wc[t];
    }
    float4 v = ((const float4*)src)[off];
    int fi   = off * 4;
    int col4 = fi & (C_DIM - 1);
    int rowb = fi - col4;
    int pb   = (col4 & ~7) + ((col4 >> 2) & 1);
    dst[rowb + pb    ] = cvt_tf32(v.x);
    dst[rowb + pb + 2] = cvt_tf32(v.y);
    dst[rowb + pb + 4] = cvt_tf32(v.z);
    dst[rowb + pb + 6] = cvt_tf32(v.w);
}

// ---------------------------------------------------------------------------
// TF32 NT GEMM (round-8 config): CTA 128x128, BK=32, 256 threads (8 warps
// 2x4), warp 64x32, SPAD=40, 2-stage cp.async, LDS.64-only mainloop.
// smem 81920 B -> 2 CTAs/SM.
// ---------------------------------------------------------------------------
#define BM 128
#define BN 128
#define BK 32
#define SPAD 40
#define STAGE_F (BM * SPAD)                 // 5120 floats
#define GEMM_SMEM (2 * 2 * STAGE_F * 4)     // 81920 bytes

__device__ __forceinline__ void issue_stage(uint32_t s_a, uint32_t s_b,
                                            const float* __restrict__ A,
                                            const float* __restrict__ W,
                                            int bm, int bn, int k0, int tid) {
    const int row0 = tid >> 3;           // 0..31
    const int c4   = (tid & 7) * 4;      // 0..28
    #pragma unroll
    for (int i = 0; i < 4; i++) {
        int r = row0 + i * 32;
        uint32_t d = s_a + (uint32_t)((r * SPAD + c4) * 4);
        CP16(d, A + (size_t)(bm + r) * C_DIM + k0 + c4);
    }
    #pragma unroll
    for (int i = 0; i < 4; i++) {
        int r = row0 + i * 32;
        uint32_t d = s_b + (uint32_t)((r * SPAD + c4) * 4);
        CP16(d, W + (size_t)(bn + r) * C_DIM + k0 + c4);
    }
}

__device__ __forceinline__ void tile_mma4(const float* __restrict__ As,
                                          const float* __restrict__ Bs,
                                          float c[4][4][4],
                                          int wm, int wn, int gid, int tig) {
    #pragma unroll
    for (int kk = 0; kk < 4; kk++) {
        const int k2 = kk * 8 + tig * 2;   // permuted col of (k, k+4) pair
        uint32_t a[4][4];
        #pragma unroll
        for (int mt = 0; mt < 4; mt++) {
            int r = wm * 64 + mt * 16 + gid;
            float2 f0 = *(const float2*)&As[(size_t)r * SPAD + k2];
            float2 f1 = *(const float2*)&As[(size_t)(r + 8) * SPAD + k2];
            a[mt][0] = __float_as_uint(f0.x);
            a[mt][1] = __float_as_uint(f1.x);
            a[mt][2] = __float_as_uint(f0.y);
            a[mt][3] = __float_as_uint(f1.y);
        }
        #pragma unroll
        for (int nt = 0; nt < 4; nt++) {
            int cn = wn * 32 + nt * 8 + gid;
            float2 fb = *(const float2*)&Bs[(size_t)cn * SPAD + k2];
            #pragma unroll
            for (int mt = 0; mt < 4; mt++)
                mma_tf32(c[mt][nt], a[mt],
                         __float_as_uint(fb.x), __float_as_uint(fb.y));
        }
    }
}

__device__ __forceinline__ void gemm_mainloop(const float* __restrict__ A,
                                              const float* __restrict__ W,
                                              float c[4][4][4],
                                              int bm, int bn, int tid) {
    extern __shared__ float dyn[];
    uint32_t sbase;
    asm("{ .reg .u64 t; cvta.to.shared.u64 t, %1; cvt.u32.u64 %0, t; }"
        : "=r"(sbase) : "l"(dyn));

    const int lane = tid & 31, wid = tid >> 5;
    const int gid = lane >> 2, tig = lane & 3;
    const int wm = wid >> 2, wn = wid & 3;

    const int NIT = C_DIM / BK;   // 32

    issue_stage(sbase, sbase + (uint32_t)(STAGE_F * 4), A, W, bm, bn, 0, tid);
    CP_COMMIT();

    for (int i = 0; i < NIT; i++) {
        CP_WAIT0();
        __syncthreads();

        int nxt = i + 1;
        if (nxt < NIT) {
            uint32_t s_a = sbase + (uint32_t)((nxt & 1) * 2 * STAGE_F * 4);
            uint32_t s_b = s_a + (uint32_t)(STAGE_F * 4);
            issue_stage(s_a, s_b, A, W, bm, bn, nxt * BK, tid);
        }
        CP_COMMIT();

        const float* As = dyn + (size_t)(i & 1) * 2 * STAGE_F;
        const float* Bs = As + STAGE_F;
        tile_mma4(As, Bs, c, wm, wn, gid, tig);
    }
}

// QKV fused. Epilogue: Q scaled+rounded+permuted, K rounded+permuted,
// V rounded natural — attention mainloop needs zero cvt.
__global__ __launch_bounds__(256, 2) void gemm_qkv_kernel()
{
    const int z = blockIdx.z;
    const float* W = g_wc[z];
    float* dst     = (z == 0) ? g_q : (z == 1) ? g_k : g_v;
    const float scale = (z == 0) ? 0.125f : 1.0f;

    const int tid = threadIdx.x;
    const int lane = tid & 31, wid = tid >> 5;
    const int gid = lane >> 2, tig = lane & 3;
    const int wm = wid >> 2, wn = wid & 3;
    const int bm = blockIdx.y * BM, bn = blockIdx.x * BN;

    float c[4][4][4];
    #pragma unroll
    for (int mt = 0; mt < 4; mt++)
        #pragma unroll
        for (int nt = 0; nt < 4; nt++)
            #pragma unroll
            for (int i = 0; i < 4; i++) c[mt][nt][i] = 0.f;

    gemm_mainloop(g_xc, W, c, bm, bn, tid);

    #pragma unroll
    for (int mt = 0; mt < 4; mt++)
        #pragma unroll
        for (int nt = 0; nt < 4; nt++) {
            int row0 = bm + wm * 64 + mt * 16 + gid;
            int n    = bn + wn * 32 + nt * 8 + tig * 2;
            int hh = n >> 6, d = n & 63;
            if (z <= 1) {
                // permuted scalar stores: pos(d), pos(d)+2 (d is even)
                int dp = (d & ~7) | ((d & 3) << 1) | ((d >> 2) & 1);
                #pragma unroll
                for (int i = 0; i < 2; i++) {
                    int m = row0 + i * 8;
                    int t = m >> 1, bb = m & 1;
                    size_t base = (((size_t)bb * H_NUM + hh) * T_SEQ + t) * D_HEAD;
                    dst[base + dp    ] = cvt_tf32(c[mt][nt][i * 2    ] * scale);
                    dst[base + dp + 2] = cvt_tf32(c[mt][nt][i * 2 + 1] * scale);
                }
            } else {
                #pragma unroll
                for (int i = 0; i < 2; i++) {
                    int m = row0 + i * 8;
                    int t = m >> 1, bb = m & 1;
                    size_t base = (((size_t)bb * H_NUM + hh) * T_SEQ + t) * D_HEAD;
                    *(float2*)&dst[base + d] =
                        make_float2(cvt_tf32(c[mt][nt][i * 2]),
                                    cvt_tf32(c[mt][nt][i * 2 + 1]));
                }
            }
        }
}

__global__ __launch_bounds__(256, 2) void gemm_out_kernel(float* __restrict__ out)
{
    const int tid = threadIdx.x;
    const int lane = tid & 31, wid = tid >> 5;
    const int gid = lane >> 2, tig = lane & 3;
    const int wm = wid >> 2, wn = wid & 3;
    const int bm = blockIdx.y * BM, bn = blockIdx.x * BN;

    float c[4][4][4];
    #pragma unroll
    for (int mt = 0; mt < 4; mt++)
        #pragma unroll
        for (int nt = 0; nt < 4; nt++)
            #pragma unroll
            for (int i = 0; i < 4; i++) c[mt][nt][i] = 0.f;

    gemm_mainloop(g_ctxp, g_wc[3], c, bm, bn, tid);

    #pragma unroll
    for (int mt = 0; mt < 4; mt++)
        #pragma unroll
        for (int nt = 0; nt < 4; nt++) {
            int row0 = bm + wm * 64 + mt * 16 + gid;
            int col0 = bn + wn * 32 + nt * 8 + tig * 2;
            *(float2*)(out + (size_t)row0 * C_DIM + col0) =
                make_float2(c[mt][nt][0], c[mt][nt][1]);
            *(float2*)(out + (size_t)(row0 + 8) * C_DIM + col0) =
                make_float2(c[mt][nt][2], c[mt][nt][3]);
        }
}

// ---------------------------------------------------------------------------
// Tensor-core causal flash attention v4: inputs pre-rounded (and K/Q
// pre-permuted), so the mainloop has no cvt and K/V staging is a plain
// double-buffered cp.async copy. 128 threads = 4 warps, Q-tile 64,
// K/V tiles 64x64 (pad 72). Dynamic smem 73728 B.
// ---------------------------------------------------------------------------
#define AT_TILE (64 * 72)            // floats per K (or V) tile
#define AT_STAGE (2 * AT_TILE)       // K + V
#define ATTN_SMEM (2 * AT_STAGE * 4) // 73728 bytes

__device__ __forceinline__ void attn_issue_kv(uint32_t sbase, int stage,
                                              const float* __restrict__ Kp,
                                              const float* __restrict__ Vp,
                                              int kb, int tid) {
    uint32_t kdst = sbase + (uint32_t)(stage * AT_STAGE * 4);
    uint32_t vdst = kdst + (uint32_t)(AT_TILE * 4);
    #pragma unroll
    for (int it = 0; it < 8; it++) {
        int idx = tid + it * 128;      // 0..1023 : 16B chunks (64 rows x 16)
        int r  = idx >> 4;             // 0..63
        int cc = (idx & 15) * 4;       // 0..60
        uint32_t off = (uint32_t)((r * 72 + cc) * 4);
        const float* srck = Kp + (size_t)(kb * 64 + r) * 64 + cc;
        const float* srcv = Vp + (size_t)(kb * 64 + r) * 64 + cc;
        CP16(kdst + off, srck);
        CP16(vdst + off, srcv);
    }
}

__global__ __launch_bounds__(128) void attn_tc_kernel()
{
    const int qb = (gridDim.x - 1) - blockIdx.x;
    const int h  = blockIdx.y;
    const int b  = blockIdx.z;
    const size_t base = (((size_t)b * H_NUM + h) * T_SEQ) * D_HEAD;
    const float* Qp = g_q + base;
    const float* Kp = g_k + base;
    const float* Vp = g_v + base;

    extern __shared__ float asm_dyn[];
    uint32_t sbase;
    asm("{ .reg .u64 t; cvta.to.shared.u64 t, %1; cvt.u32.u64 %0, t; }"
        : "=r"(sbase) : "l"(asm_dyn));

    const int tid  = threadIdx.x;
    const int lane = tid & 31;
    const int wid  = tid >> 5;
    const int gid  = lane >> 2;
    const int tig  = lane & 3;

    const int t0 = qb * 64 + wid * 16 + gid;
    const int t1 = t0 + 8;

    // Q a-frags: pre-scaled/rounded/permuted -> float2 loads, no math
    uint32_t qa[8][4];
    #pragma unroll
    for (int kk = 0; kk < 8; kk++) {
        float2 f0 = *(const float2*)(Qp + (size_t)t0 * 64 + kk * 8 + tig * 2);
        float2 f1 = *(const float2*)(Qp + (size_t)t1 * 64 + kk * 8 + tig * 2);
        qa[kk][0] = __float_as_uint(f0.x);
        qa[kk][1] = __float_as_uint(f1.x);
        qa[kk][2] = __float_as_uint(f0.y);
        qa[kk][3] = __float_as_uint(f1.y);
    }

    float m0 = -1e30f, m1 = -1e30f, l0 = 0.f, l1 = 0.f;
    float o[8][4];
    #pragma unroll
    for (int nt = 0; nt < 8; nt++)
        #pragma unroll
        for (int i = 0; i < 4; i++) o[nt][i] = 0.f;

    const int nkb = qb + 1;

    attn_issue_kv(sbase, 0, Kp, Vp, 0, tid);
    CP_COMMIT();

    for (int kb = 0; kb < nkb; kb++) {
        if (kb + 1 < nkb) {
            attn_issue_kv(sbase, (kb + 1) & 1, Kp, Vp, kb + 1, tid);
            CP_COMMIT();
            CP_WAIT1();
        } else {
            CP_WAIT0();
        }
        __syncthreads();

        const float* Ks = asm_dyn + (size_t)(kb & 1) * AT_STAGE;
        const float* Vs = Ks + AT_TILE;

        float s[8][4];
        #pragma unroll
        for (int nt = 0; nt < 8; nt++)
            #pragma unroll
            for (int i = 0; i < 4; i++) s[nt][i] = 0.f;

        #pragma unroll
        for (int kk = 0; kk < 8; kk++) {
            #pragma unroll
            for (int nt = 0; nt < 8; nt++) {
                float2 kbf = *(const float2*)&Ks[(size_t)(nt * 8 + gid) * 72 + kk * 8 + tig * 2];
                mma_tf32(s[nt], qa[kk], __float_as_uint(kbf.x), __float_as_uint(kbf.y));
            }
        }

        if (kb == qb) {
            #pragma unroll
            for (int nt = 0; nt < 8; nt++) {
                int cg = kb * 64 + nt * 8 + tig * 2;
                if (cg     > t0) s[nt][0] = -1e30f;
                if (cg + 1 > t0) s[nt][1] = -1e30f;
                if (cg     > t1) s[nt][2] = -1e30f;
                if (cg + 1 > t1) s[nt][3] = -1e30f;
            }
        }

        float mb0 = m0, mb1 = m1;
        #pragma unroll
        for (int nt = 0; nt < 8; nt++) {
            mb0 = fmaxf(mb0, fmaxf(s[nt][0], s[nt][1]));
            mb1 = fmaxf(mb1, fmaxf(s[nt][2], s[nt][3]));
        }
        mb0 = fmaxf(mb0, __shfl_xor_sync(0xffffffffu, mb0, 1));
        mb0 = fmaxf(mb0, __shfl_xor_sync(0xffffffffu, mb0, 2));
        mb1 = fmaxf(mb1, __shfl_xor_sync(0xffffffffu, mb1, 1));
        mb1 = fmaxf(mb1, __shfl_xor_sync(0xffffffffu, mb1, 2));

        float corr0 = fast_exp(m0 - mb0);
        float corr1 = fast_exp(m1 - mb1);
        m0 = mb0; m1 = mb1;
        l0 *= corr0; l1 *= corr1;
        #pragma unroll
        for (int nt = 0; nt < 8; nt++) {
            o[nt][0] *= corr0; o[nt][1] *= corr0;
            o[nt][2] *= corr1; o[nt][3] *= corr1;
        }

        #pragma unroll
        for (int nt = 0; nt < 8; nt++) {
            s[nt][0] = fast_exp(s[nt][0] - m0);
            s[nt][1] = fast_exp(s[nt][1] - m0);
            s[nt][2] = fast_exp(s[nt][2] - m1);
            s[nt][3] = fast_exp(s[nt][3] - m1);
            l0 += s[nt][0] + s[nt][1];
            l1 += s[nt][2] + s[nt][3];
        }

        #pragma unroll
        for (int kk = 0; kk < 8; kk++) {
            int src  = (lane & ~3) | (tig >> 1);
            int src2 = src + 2;
            float v00 = __shfl_sync(0xffffffffu, s[kk][0], src);
            float v01 = __shfl_sync(0xffffffffu, s[kk][1], src);
            float v10 = __shfl_sync(0xffffffffu, s[kk][2], src);
            float v11 = __shfl_sync(0xffffffffu, s[kk][3], src);
            float w00 = __shfl_sync(0xffffffffu, s[kk][0], src2);
            float w01 = __shfl_sync(0xffffffffu, s[kk][1], src2);
            float w10 = __shfl_sync(0xffffffffu, s[kk][2], src2);
            float w11 = __shfl_sync(0xffffffffu, s[kk][3], src2);
            bool odd = (tig & 1);
            uint32_t pa[4];
            pa[0] = __float_as_uint(cvt_tf32(odd ? v01 : v00));
            pa[1] = __float_as_uint(cvt_tf32(odd ? v11 : v10));
            pa[2] = __float_as_uint(cvt_tf32(odd ? w01 : w00));
            pa[3] = __float_as_uint(cvt_tf32(odd ? w11 : w10));
            #pragma unroll
            for (int nt = 0; nt < 8; nt++) {
                uint32_t b0 = __float_as_uint(Vs[(size_t)(kk * 8 + tig    ) * 72 + nt * 8 + gid]);
                uint32_t b1 = __float_as_uint(Vs[(size_t)(kk * 8 + tig + 4) * 72 + nt * 8 + gid]);
                mma_tf32(o[nt], pa, b0, b1);
            }
        }
        __syncthreads();
    }

    l0 += __shfl_xor_sync(0xffffffffu, l0, 1);
    l0 += __shfl_xor_sync(0xffffffffu, l0, 2);
    l1 += __shfl_xor_sync(0xffffffffu, l1, 1);
    l1 += __shfl_xor_sync(0xffffffffu, l1, 2);
    float inv0 = 1.f / l0;
    float inv1 = 1.f / l1;

    // write ctx rounded + column-permuted (within groups of 8)
    const int k0 = tig * 2;
    const int p0 = ((k0 & 3) << 1) | ((k0 >> 2) & 1);
    const int p1 = (((k0 + 1) & 3) << 1) | (((k0 + 1) >> 2) & 1);
    #pragma unroll
    for (int nt = 0; nt < 8; nt++) {
        int cb = h * 64 + nt * 8;
        size_t r0 = ((size_t)t0 * B_SZ + b) * C_DIM + cb;
        size_t r1 = ((size_t)t1 * B_SZ + b) * C_DIM + cb;
        g_ctxp[r0 + p0] = cvt_tf32(o[nt][0] * inv0);
        g_ctxp[r0 + p1] = cvt_tf32(o[nt][1] * inv0);
        g_ctxp[r1 + p0] = cvt_tf32(o[nt][2] * inv1);
        g_ctxp[r1 + p1] = cvt_tf32(o[nt][3] * inv1);
    }
}

// ---------------------------------------------------------------------------
extern "C" void kernel_launch(void* const* d_in, const int* in_sizes, int n_in,
                              void* d_out, int out_size)
{
    const float* x  = (const float*)d_in[0];
    const float* Wq = (const float*)d_in[1];
    const float* Wk = (const float*)d_in[2];
    const float* Wv = (const float*)d_in[3];
    const float* Wo = (const float*)d_in[4];
    float* out = (float*)d_out;

    cudaFuncSetAttribute(gemm_qkv_kernel,
                         cudaFuncAttributeMaxDynamicSharedMemorySize, GEMM_SMEM);
    cudaFuncSetAttribute(gemm_out_kernel,
                         cudaFuncAttributeMaxDynamicSharedMemorySize, GEMM_SMEM);
    cudaFuncSetAttribute(attn_tc_kernel,
                         cudaFuncAttributeMaxDynamicSharedMemorySize, ATTN_SMEM);

    int nconv = (X_F4 + 4 * W_F4) / 256;     // 8192 blocks
    preconvert_kernel<<<nconv, 256>>>(x, Wq, Wk, Wv, Wo);

    dim3 gq(C_DIM / BN, M_ROWS / BM, 3);     // (8, 32, 3)
    gemm_qkv_kernel<<<gq, 256, GEMM_SMEM>>>();

    dim3 ga(T_SEQ / 64, H_NUM, B_SZ);        // (32, 16, 2)
    attn_tc_kernel<<<ga, 128, ATTN_SMEM>>>();

    dim3 go(C_DIM / BN, M_ROWS / BM);        // (8, 32)
    gemm_out_kernel<<<go, 256, GEMM_SMEM>>>(out);
}